// round 16
// baseline (speedup 1.0000x reference)
#include <cuda_runtime.h>
#include <cuda_bf16.h>
#include <cuda_fp16.h>
#include <cstdint>

#define BATCH 4
#define SEQ   2048
#define FD    256
#define NH    4
#define DH    64
#define CHK   256
#define NCHUNK 8

typedef unsigned long long ull;
typedef uint32_t u32;

// ---------------- device scratch ----------------
__device__ __nv_bfloat16 g_xh[BATCH*SEQ*FD];   // bf16 hi (K path)
__device__ __nv_bfloat16 g_xl[BATCH*SEQ*FD];   // bf16 lo (K path)
__device__ __nv_bfloat16 g_xf[BATCH*SEQ*FD];   // fp16 single (Q/V path)
__device__ __nv_bfloat16 g_qf[BATCH*SEQ*FD];   // fp16 single
__device__ __nv_bfloat16 g_kh[BATCH*SEQ*FD];   // fp16 hi
__device__ __nv_bfloat16 g_kl[BATCH*SEQ*FD];   // fp16 lo
__device__ __nv_bfloat16 g_vh[BATCH*SEQ*FD];   // fp16 single
__device__ __nv_bfloat16 g_ch[BATCH*SEQ*FD];   // ctx bf16 hi
__device__ __nv_bfloat16 g_cl[BATCH*SEQ*FD];   // ctx bf16 lo
__device__ __nv_bfloat16 g_wqh[FD*FD], g_wql[FD*FD];   // fp16 hi/lo (scaled)
__device__ __nv_bfloat16 g_wkh[FD*FD], g_wkl[FD*FD];   // bf16 hi/lo
__device__ __nv_bfloat16 g_wvh[FD*FD], g_wvl[FD*FD];   // fp16 hi/lo
__device__ __nv_bfloat16 g_woh[FD*FD], g_wol[FD*FD];   // bf16 hi/lo
__device__ unsigned g_adjb[SEQ * (SEQ/32)];

// ---------------- helpers ----------------
__device__ __forceinline__ u32 smem_u32(const void* p) {
  u32 a; asm("{ .reg .u64 t; cvta.to.shared.u64 t, %1; cvt.u32.u64 %0, t; }"
             : "=r"(a) : "l"(p)); return a;
}
__device__ __forceinline__ float ex2f(float x) {
  float r; asm("ex2.approx.f32 %0, %1;" : "=f"(r) : "f"(x)); return r;
}
__device__ __forceinline__ float rcpf(float x) {
  float r; asm("rcp.approx.f32 %0, %1;" : "=f"(r) : "f"(x)); return r;
}
__device__ __forceinline__ void tsplit2(float x0, float x1, u32& hw, u32& lw) {
  u32 b0 = __float_as_uint(x0), b1 = __float_as_uint(x1);
  u32 h0 = b0 & 0xFFFF0000u, h1 = b1 & 0xFFFF0000u;
  hw = (b0 >> 16) | h1;
  float l0 = x0 - __uint_as_float(h0);
  float l1 = x1 - __uint_as_float(h1);
  asm("cvt.rn.bf16x2.f32 %0, %1, %2;" : "=r"(lw) : "f"(l1), "f"(l0));
}
__device__ __forceinline__ void hsplit2(float x0, float x1, u32& hw, u32& lw) {
  u32 h;
  asm("cvt.rn.f16x2.f32 %0, %1, %2;" : "=r"(h) : "f"(x1), "f"(x0));
  __half2 hh = *reinterpret_cast<__half2*>(&h);
  float r0 = x0 - __low2float(hh);
  float r1 = x1 - __high2float(hh);
  hw = h;
  asm("cvt.rn.f16x2.f32 %0, %1, %2;" : "=r"(lw) : "f"(r1), "f"(r0));
}
__device__ __forceinline__ u32 hpack2(float x0, float x1) {
  u32 h;
  asm("cvt.rn.f16x2.f32 %0, %1, %2;" : "=r"(h) : "f"(x1), "f"(x0));
  return h;
}
__device__ __forceinline__ void ldsm4(u32* r, u32 addr) {
  asm volatile("ldmatrix.sync.aligned.m8n8.x4.shared.b16 {%0,%1,%2,%3}, [%4];"
    : "=r"(r[0]), "=r"(r[1]), "=r"(r[2]), "=r"(r[3]) : "r"(addr));
}
__device__ __forceinline__ void ldsm4t(u32* r, u32 addr) {
  asm volatile("ldmatrix.sync.aligned.m8n8.x4.trans.shared.b16 {%0,%1,%2,%3}, [%4];"
    : "=r"(r[0]), "=r"(r[1]), "=r"(r[2]), "=r"(r[3]) : "r"(addr));
}
__device__ __forceinline__ void mma16816(float* d, const u32* a, u32 b0, u32 b1) {
  asm volatile("mma.sync.aligned.m16n8k16.row.col.f32.bf16.bf16.f32 "
    "{%0,%1,%2,%3}, {%4,%5,%6,%7}, {%8,%9}, {%0,%1,%2,%3};"
    : "+f"(d[0]), "+f"(d[1]), "+f"(d[2]), "+f"(d[3])
    : "r"(a[0]), "r"(a[1]), "r"(a[2]), "r"(a[3]), "r"(b0), "r"(b1));
}
__device__ __forceinline__ void mma16816h(float* d, const u32* a, u32 b0, u32 b1) {
  asm volatile("mma.sync.aligned.m16n8k16.row.col.f32.f16.f16.f32 "
    "{%0,%1,%2,%3}, {%4,%5,%6,%7}, {%8,%9}, {%0,%1,%2,%3};"
    : "+f"(d[0]), "+f"(d[1]), "+f"(d[2]), "+f"(d[3])
    : "r"(a[0]), "r"(a[1]), "r"(a[2]), "r"(a[3]), "r"(b0), "r"(b1));
}
#define CPA16(dst, src) \
  asm volatile("cp.async.cg.shared.global [%0], [%1], 16;" \
               :: "r"(dst), "l"(src) : "memory")
#define CPA_FENCE() do { \
  asm volatile("cp.async.commit_group;" ::: "memory"); \
  asm volatile("cp.async.wait_group 0;" ::: "memory"); \
} while (0)

// ---------------- fused prep: adj pack + x split + w split ----------------
// blocks [0,512): adj; [512,2560): x; [2560,3072): w
__global__ void prep_kernel(
    const int* __restrict__ adj, unsigned* __restrict__ adjb,
    const float* __restrict__ x,
    __nv_bfloat16* __restrict__ xh, __nv_bfloat16* __restrict__ xl,
    __nv_bfloat16* __restrict__ xf,
    const float* __restrict__ Wq, const float* __restrict__ Wk,
    const float* __restrict__ Wv, const float* __restrict__ Wo,
    __nv_bfloat16* __restrict__ wqh, __nv_bfloat16* __restrict__ wql,
    __nv_bfloat16* __restrict__ wkh, __nv_bfloat16* __restrict__ wkl,
    __nv_bfloat16* __restrict__ wvh, __nv_bfloat16* __restrict__ wvl,
    __nv_bfloat16* __restrict__ woh, __nv_bfloat16* __restrict__ wol,
    float qs) {
  const int bx = blockIdx.x;
  const int t = threadIdx.x;
  if (bx < 512) {
    const int idx = bx * 256 + t;
    const int4* p = (const int4*)(adj + (size_t)idx * 32);
    unsigned b = 0;
    #pragma unroll
    for (int u = 0; u < 8; u++) {
      int4 v = p[u];
      b |= (v.x != 0 ? 1u : 0u) << (u*4 + 0);
      b |= (v.y != 0 ? 1u : 0u) << (u*4 + 1);
      b |= (v.z != 0 ? 1u : 0u) << (u*4 + 2);
      b |= (v.w != 0 ? 1u : 0u) << (u*4 + 3);
    }
    adjb[idx] = b;
  } else if (bx < 2560) {
    const int i = ((bx - 512) * 256 + t) * 4;
    float4 v = *(const float4*)&x[i];
    u32 h0, l0, h1, l1;
    tsplit2(v.x, v.y, h0, l0);
    tsplit2(v.z, v.w, h1, l1);
    *(u32*)&xh[i]   = h0; *(u32*)&xh[i+2] = h1;
    *(u32*)&xl[i]   = l0; *(u32*)&xl[i+2] = l1;
    *(u32*)&xf[i]   = hpack2(v.x, v.y);
    *(u32*)&xf[i+2] = hpack2(v.z, v.w);
  } else {
    const int bw = bx - 2560;              // 512 blocks, 128 per matrix
    const int m = bw >> 7;
    const int i = ((bw & 127) * 256 + t) * 2;
    const float* src = (m == 0) ? Wq : (m == 1) ? Wk : (m == 2) ? Wv : Wo;
    __nv_bfloat16* dh = (m == 0) ? wqh : (m == 1) ? wkh : (m == 2) ? wvh : woh;
    __nv_bfloat16* dl = (m == 0) ? wql : (m == 1) ? wkl : (m == 2) ? wvl : wol;
    const float s = (m == 0) ? qs : 1.f;
    float2 v = *(const float2*)&src[i];
    u32 hw, lw;
    if (m == 0 || m == 2) hsplit2(v.x * s, v.y * s, hw, lw);
    else                  tsplit2(v.x, v.y, hw, lw);
    *(u32*)&dh[i] = hw;
    *(u32*)&dl[i] = lw;
  }
}

// ---------------- QKV HMMA GEMM: 64x128 tile, 128 threads ----------------
// Q/V path: A = xf (fp16 single), W fp16 hi/lo, 2-pass fp16 mma, out fp16.
// K path:   A = xh/xl (bf16),     W bf16 hi/lo, 3-pass bf16 mma, out fp16 hi/lo.
#define GP 144
#define GOF_AH 0
#define GOF_AL 9216
#define GOF_WH 18432
#define GOF_WL 36864
#define GEMM_SMEM 55296

__global__ void __launch_bounds__(128, 3) qkv_hmma_kernel(
    const __nv_bfloat16* __restrict__ xh, const __nv_bfloat16* __restrict__ xl,
    const __nv_bfloat16* __restrict__ xf,
    const __nv_bfloat16* __restrict__ wqh, const __nv_bfloat16* __restrict__ wql,
    const __nv_bfloat16* __restrict__ wkh, const __nv_bfloat16* __restrict__ wkl,
    const __nv_bfloat16* __restrict__ wvh, const __nv_bfloat16* __restrict__ wvl,
    const float* __restrict__ bq, const float* __restrict__ bk,
    const float* __restrict__ bv,
    __nv_bfloat16* __restrict__ qf,
    __nv_bfloat16* __restrict__ kh, __nv_bfloat16* __restrict__ kl,
    __nv_bfloat16* __restrict__ vh,
    float qs) {
  extern __shared__ __align__(16) char smem[];
  const int p = blockIdx.y >> 1, half = blockIdx.y & 1;
  const bool kpath = (p == 1);
  const __nv_bfloat16* Wh = (p == 0) ? wqh : (p == 1) ? wkh : wvh;
  const __nv_bfloat16* Wl = (p == 0) ? wql : (p == 1) ? wkl : wvl;
  const float* bias = (p == 0) ? bq : (p == 1) ? bk : bv;
  __nv_bfloat16* Ch = (p == 0) ? qf : (p == 1) ? kh : vh;
  const float sb = (p == 0) ? qs : 1.f;
  const int m0 = blockIdx.x * 64, n0g = half * 128;

  const u32 smb = smem_u32(smem);
  const int t = threadIdx.x;
  const int w = t >> 5, l = t & 31;
  const int gr = l >> 2, tg = l & 3;

  float acc[16][4];
  #pragma unroll
  for (int nt = 0; nt < 16; nt++)
    #pragma unroll
    for (int d = 0; d < 4; d++) acc[nt][d] = 0.f;

  for (int kc = 0; kc < 4; kc++) {
    const int k0 = kc * 64;
    __syncthreads();
    if (kpath) {
      #pragma unroll
      for (int i = 0; i < 4; i++) {
        int idx = t + i * 128;
        int r = idx >> 3, c = idx & 7;
        u32 so = r * GP + c * 16;
        size_t ga = ((size_t)(m0 + r) * FD + k0) * 2 + c * 16;
        CPA16(smb + GOF_AH + so, (const char*)xh + ga);
        CPA16(smb + GOF_AL + so, (const char*)xl + ga);
      }
    } else {
      #pragma unroll
      for (int i = 0; i < 4; i++) {
        int idx = t + i * 128;
        int r = idx >> 3, c = idx & 7;
        u32 so = r * GP + c * 16;
        size_t ga = ((size_t)(m0 + r) * FD + k0) * 2 + c * 16;
        CPA16(smb + GOF_AH + so, (const char*)xf + ga);
      }
    }
    #pragma unroll
    for (int i = 0; i < 8; i++) {
      int idx = t + i * 128;
      int r = idx >> 3, c = idx & 7;
      u32 so = r * GP + c * 16;
      size_t gw = ((size_t)(n0g + r) * FD + k0) * 2 + c * 16;
      CPA16(smb + GOF_WH + so, (const char*)Wh + gw);
      CPA16(smb + GOF_WL + so, (const char*)Wl + gw);
    }
    CPA_FENCE();
    __syncthreads();

    const u32 lrow = (u32)(l & 15) * GP;
    const u32 chi  = (u32)(l >> 4) * 16;
    if (kpath) {
      #pragma unroll
      for (int ks = 0; ks < 4; ks++) {
        u32 aa = smb + GOF_AH + (u32)(w * 16) * GP + lrow + ks * 32 + chi;
        u32 ah[4], al2[4];
        ldsm4(ah, aa);
        ldsm4(al2, aa + (GOF_AL - GOF_AH));
        #pragma unroll
        for (int g = 0; g < 8; g++) {
          u32 wa = smb + GOF_WH + (u32)(g * 16) * GP + lrow + ks * 32 + chi;
          u32 bh[4], bl[4];
          ldsm4(bh, wa);
          ldsm4(bl, wa + (GOF_WL - GOF_WH));
          mma16816(acc[2*g],   ah,  bh[0], bh[2]);
          mma16816(acc[2*g+1], ah,  bh[1], bh[3]);
          mma16816(acc[2*g],   ah,  bl[0], bl[2]);
          mma16816(acc[2*g+1], ah,  bl[1], bl[3]);
          mma16816(acc[2*g],   al2, bh[0], bh[2]);
          mma16816(acc[2*g+1], al2, bh[1], bh[3]);
        }
      }
    } else {
      #pragma unroll
      for (int ks = 0; ks < 4; ks++) {
        u32 aa = smb + GOF_AH + (u32)(w * 16) * GP + lrow + ks * 32 + chi;
        u32 af[4];
        ldsm4(af, aa);
        #pragma unroll
        for (int g = 0; g < 8; g++) {
          u32 wa = smb + GOF_WH + (u32)(g * 16) * GP + lrow + ks * 32 + chi;
          u32 bh[4], bl[4];
          ldsm4(bh, wa);
          ldsm4(bl, wa + (GOF_WL - GOF_WH));
          mma16816h(acc[2*g],   af, bh[0], bh[2]);
          mma16816h(acc[2*g+1], af, bh[1], bh[3]);
          mma16816h(acc[2*g],   af, bl[0], bl[2]);
          mma16816h(acc[2*g+1], af, bl[1], bl[3]);
        }
      }
    }
  }

  const int mrow = m0 + w * 16 + gr;
  #pragma unroll
  for (int nt = 0; nt < 16; nt++) {
    const int n = n0g + nt * 8 + 2 * tg;
    const float bx = bias[n] * sb, by = bias[n + 1] * sb;
    float c00 = acc[nt][0] + bx, c01 = acc[nt][1] + by;
    float c10 = acc[nt][2] + bx, c11 = acc[nt][3] + by;
    if (kpath) {
      u32 hw, lw;
      hsplit2(c00, c01, hw, lw);
      *(u32*)&kh[(size_t)mrow * FD + n] = hw;
      *(u32*)&kl[(size_t)mrow * FD + n] = lw;
      hsplit2(c10, c11, hw, lw);
      *(u32*)&kh[(size_t)(mrow + 8) * FD + n] = hw;
      *(u32*)&kl[(size_t)(mrow + 8) * FD + n] = lw;
    } else {
      *(u32*)&Ch[(size_t)mrow * FD + n]       = hpack2(c00, c01);
      *(u32*)&Ch[(size_t)(mrow + 8) * FD + n] = hpack2(c10, c11);
    }
  }
}

// ---------------- Fused O-projection + residual + LayerNorm ----------------
#define OO_AH 0
#define OO_AL 9216
#define OO_WH 18432
#define OO_WL (18432 + 36864)
#define O_SMEM (18432 + 2*36864)   // 92160

__global__ void __launch_bounds__(128, 1) o_ln_kernel(
    const __nv_bfloat16* __restrict__ ch, const __nv_bfloat16* __restrict__ cl,
    const __nv_bfloat16* __restrict__ woh, const __nv_bfloat16* __restrict__ wol,
    const float* __restrict__ bo, const float* __restrict__ x,
    const float* __restrict__ gamma, const float* __restrict__ beta,
    float* __restrict__ out) {
  extern __shared__ __align__(16) char smem[];
  const u32 smb = smem_u32(smem);
  const int m0 = blockIdx.x * 64;
  const int t = threadIdx.x;
  const int w = t >> 5, l = t & 31;
  const int gr = l >> 2, tg = l & 3;

  float acc[32][4];
  #pragma unroll
  for (int nt = 0; nt < 32; nt++)
    #pragma unroll
    for (int d = 0; d < 4; d++) acc[nt][d] = 0.f;

  for (int kc = 0; kc < 4; kc++) {
    const int k0 = kc * 64;
    __syncthreads();
    #pragma unroll
    for (int i = 0; i < 4; i++) {
      int idx = t + i * 128;
      int r = idx >> 3, c = idx & 7;
      u32 so = r * GP + c * 16;
      size_t ga = ((size_t)(m0 + r) * FD + k0) * 2 + c * 16;
      CPA16(smb + OO_AH + so, (const char*)ch + ga);
      CPA16(smb + OO_AL + so, (const char*)cl + ga);
    }
    #pragma unroll
    for (int i = 0; i < 16; i++) {
      int idx = t + i * 128;
      int r = idx >> 3, c = idx & 7;
      u32 so = r * GP + c * 16;
      size_t gw = ((size_t)r * FD + k0) * 2 + c * 16;
      CPA16(smb + OO_WH + so, (const char*)woh + gw);
      CPA16(smb + OO_WL + so, (const char*)wol + gw);
    }
    CPA_FENCE();
    __syncthreads();

    const u32 lrow = (u32)(l & 15) * GP;
    const u32 chi  = (u32)(l >> 4) * 16;
    #pragma unroll
    for (int ks = 0; ks < 4; ks++) {
      u32 aa = smb + OO_AH + (u32)(w * 16) * GP + lrow + ks * 32 + chi;
      u32 ah[4], al2[4];
      ldsm4(ah, aa);
      ldsm4(al2, aa + (OO_AL - OO_AH));
      #pragma unroll
      for (int g = 0; g < 16; g++) {
        u32 wa = smb + OO_WH + (u32)(g * 16) * GP + lrow + ks * 32 + chi;
        u32 bh[4], bl[4];
        ldsm4(bh, wa);
        ldsm4(bl, wa + (OO_WL - OO_WH));
        mma16816(acc[2*g],   ah,  bh[0], bh[2]);
        mma16816(acc[2*g+1], ah,  bh[1], bh[3]);
        mma16816(acc[2*g],   ah,  bl[0], bl[2]);
        mma16816(acc[2*g+1], ah,  bl[1], bl[3]);
        mma16816(acc[2*g],   al2, bh[0], bh[2]);
        mma16816(acc[2*g+1], al2, bh[1], bh[3]);
      }
    }
  }

  const int r0 = m0 + w * 16 + gr;
  const int r1 = r0 + 8;
  float s1a = 0.f, s2a = 0.f, s1b = 0.f, s2b = 0.f;
  #pragma unroll
  for (int nt = 0; nt < 32; nt++) {
    const int n = nt * 8 + 2 * tg;
    const float2 bb = *(const float2*)&bo[n];
    const float2 x0 = *(const float2*)&x[(size_t)r0 * FD + n];
    const float2 x1 = *(const float2*)&x[(size_t)r1 * FD + n];
    acc[nt][0] += bb.x + x0.x;
    acc[nt][1] += bb.y + x0.y;
    acc[nt][2] += bb.x + x1.x;
    acc[nt][3] += bb.y + x1.y;
    s1a += acc[nt][0] + acc[nt][1];
    s2a += acc[nt][0]*acc[nt][0] + acc[nt][1]*acc[nt][1];
    s1b += acc[nt][2] + acc[nt][3];
    s2b += acc[nt][2]*acc[nt][2] + acc[nt][3]*acc[nt][3];
  }
  #pragma unroll
  for (int off = 1; off <= 2; off <<= 1) {
    s1a += __shfl_xor_sync(0xFFFFFFFFu, s1a, off);
    s2a += __shfl_xor_sync(0xFFFFFFFFu, s2a, off);
    s1b += __shfl_xor_sync(0xFFFFFFFFu, s1b, off);
    s2b += __shfl_xor_sync(0xFFFFFFFFu, s2b, off);
  }
  const float mua = s1a * (1.f / FD);
  const float mub = s1b * (1.f / FD);
  const float ra = rsqrtf(s2a * (1.f / FD) - mua * mua + 1e-5f);
  const float rb = rsqrtf(s2b * (1.f / FD) - mub * mub + 1e-5f);

  #pragma unroll
  for (int nt = 0; nt < 32; nt++) {
    const int n = nt * 8 + 2 * tg;
    const float2 gg = *(const float2*)&gamma[n];
    const float2 be = *(const float2*)&beta[n];
    float2 o0, o1;
    o0.x = (acc[nt][0] - mua) * ra * gg.x + be.x;
    o0.y = (acc[nt][1] - mua) * ra * gg.y + be.y;
    o1.x = (acc[nt][2] - mub) * rb * gg.x + be.x;
    o1.y = (acc[nt][3] - mub) * rb * gg.y + be.y;
    *(float2*)&out[(size_t)r0 * FD + n] = o0;
    *(float2*)&out[(size_t)r1 * FD + n] = o1;
  }
}

// ---------------- HMMA attention: fp16 S (Qf x Khi/Klo) + fp16 PV ----------
#define AP 144
#define AOF_Q  0
#define AOF_KH 9216
#define AOF_KL (AOF_KH + 18432)
#define AOF_VH (AOF_KL + 18432)
#define AOF_ADJ (AOF_VH + 18432)      // 64512
#define SM_ATTN (AOF_ADJ + 2048)      // 66560

__global__ void __launch_bounds__(128, 3) attn_hmma_kernel(
    const __nv_bfloat16* __restrict__ qf,
    const __nv_bfloat16* __restrict__ kh, const __nv_bfloat16* __restrict__ kl,
    const __nv_bfloat16* __restrict__ vh,
    const unsigned* __restrict__ adjb,
    __nv_bfloat16* __restrict__ ctxh, __nv_bfloat16* __restrict__ ctxl) {
  extern __shared__ __align__(16) char smem[];
  const u32 smb = smem_u32(smem);
  unsigned* adj_s = (unsigned*)(smem + AOF_ADJ);

  const int b  = blockIdx.z;
  const int h  = blockIdx.y;
  const int n0 = blockIdx.x * 64;
  const int t  = threadIdx.x;
  const int w  = t >> 5;
  const int l  = t & 31;
  const int gr = l >> 2, tg = l & 3;

  const float CLIP = 14.426950408889634f;
  const float ENEG = 4.5399929762484854e-05f;

  {
    const char* gq = (const char*)(qf + ((size_t)b*SEQ + n0)*FD + h*DH);
    #pragma unroll
    for (int i = 0; i < 4; i++) {
      int idx = t + i * 128;
      int r = idx >> 3, c = idx & 7;
      CPA16(smb + AOF_Q + r * AP + c * 16, gq + (size_t)r*512 + c*16);
    }
    CPA_FENCE();
  }
  __syncthreads();

  u32 qfr[4][4];
  {
    const u32 rowoff = (u32)(w*16 + (l & 15)) * AP;
    const u32 coloff = (u32)((l >> 4) * 8) * 2;
    #pragma unroll
    for (int ks = 0; ks < 4; ks++)
      ldsm4(qfr[ks], smb + AOF_Q + rowoff + ks*32 + coloff);
  }

  float ctxa[8][4];
  #pragma unroll
  for (int i = 0; i < 8; i++)
    #pragma unroll
    for (int d = 0; d < 4; d++) ctxa[i][d] = 0.f;

  const char* gkh = (const char*)(kh + ((size_t)b*SEQ)*FD + h*DH);
  const char* gkl = (const char*)(kl + ((size_t)b*SEQ)*FD + h*DH);
  const char* gvh = (const char*)(vh + ((size_t)b*SEQ)*FD + h*DH);

  const int lr0 = w*16 + gr;

  for (int j = 0; j < NCHUNK; ++j) {
    __syncthreads();

    #pragma unroll
    for (int i = 0; i < 4; i++) {
      int idx = t + i * 128;
      int row = idx >> 3, wi = idx & 7;
      adj_s[idx] = adjb[(size_t)(n0 + row) * (SEQ/32) + j * 8 + wi];
    }

    float rs0 = 0.f, rs1 = 0.f;
    float cU[8][4];
    #pragma unroll
    for (int i = 0; i < 8; i++)
      #pragma unroll
      for (int d = 0; d < 4; d++) cU[i][d] = 0.f;

    for (int hf = 0; hf < 2; hf++) {
      if (hf) __syncthreads();
      {
        const size_t gb = (size_t)(j * CHK + hf * 128) * 512;
        #pragma unroll
        for (int i = 0; i < 8; i++) {
          int idx = t + i * 128;
          int r = idx >> 3, c = idx & 7;
          size_t go = gb + (size_t)r*512 + c*16;
          u32 so = r * AP + c * 16;
          CPA16(smb + AOF_KH + so, gkh + go);
          CPA16(smb + AOF_KL + so, gkl + go);
          CPA16(smb + AOF_VH + so, gvh + go);
        }
        CPA_FENCE();
      }
      __syncthreads();

      #pragma unroll
      for (int kb = 0; kb < 2; kb++) {
        const int key0 = kb * 64;
        float S[8][4];
        #pragma unroll
        for (int i = 0; i < 8; i++)
          #pragma unroll
          for (int d = 0; d < 4; d++) S[i][d] = 0.f;

        const u32 lrow16 = (u32)(l & 15) * AP;
        const u32 chi = (u32)((l >> 4) * 8) * 2;
        #pragma unroll
        for (int ks = 0; ks < 4; ks++) {
          #pragma unroll
          for (int g = 0; g < 4; g++) {
            u32 a = smb + AOF_KH + (u32)(key0 + g*16)*AP + lrow16 + ks*32 + chi;
            u32 kf[4], kf2[4];
            ldsm4(kf,  a);
            ldsm4(kf2, a + (AOF_KL - AOF_KH));
            mma16816h(S[2*g],   qfr[ks], kf[0],  kf[2]);
            mma16816h(S[2*g+1], qfr[ks], kf[1],  kf[3]);
            mma16816h(S[2*g],   qfr[ks], kf2[0], kf2[2]);
            mma16816h(S[2*g+1], qfr[ks], kf2[1], kf2[3]);
          }
        }

        const int wbase = lr0*8 + hf*4 + kb*2;
        const u32 w00 = adj_s[wbase + 0];
        const u32 w01 = adj_s[wbase + 1];
        const u32 w10 = adj_s[wbase + 64 + 0];
        const u32 w11 = adj_s[wbase + 64 + 1];
        u32 Pf0[8], Pf1[8];
        #pragma unroll
        for (int nt = 0; nt < 8; nt++) {
          const u32 a0w = (nt < 4) ? w00 : w01;
          const u32 a1w = (nt < 4) ? w10 : w11;
          const int bit = (nt & 3) * 8 + 2 * tg;
          float x;
          x = fminf(fmaxf(S[nt][0], -CLIP), CLIP);
          float e00 = ((a0w >> bit) & 1u)     ? ex2f(x) : ENEG;
          x = fminf(fmaxf(S[nt][1], -CLIP), CLIP);
          float e01 = ((a0w >> (bit+1)) & 1u) ? ex2f(x) : ENEG;
          x = fminf(fmaxf(S[nt][2], -CLIP), CLIP);
          float e10 = ((a1w >> bit) & 1u)     ? ex2f(x) : ENEG;
          x = fminf(fmaxf(S[nt][3], -CLIP), CLIP);
          float e11 = ((a1w >> (bit+1)) & 1u) ? ex2f(x) : ENEG;
          rs0 += e00 + e01;
          rs1 += e10 + e11;
          Pf0[nt] = hpack2(e00, e01);
          Pf1[nt] = hpack2(e10, e11);
        }

        #pragma unroll
        for (int kt = 0; kt < 4; kt++) {
          u32 Af[4] = { Pf0[2*kt], Pf1[2*kt], Pf0[2*kt+1], Pf1[2*kt+1] };
          const u32 vrow = (u32)(key0 + kt*16) * AP + lrow16;
          #pragma unroll
          for (int dg = 0; dg < 4; dg++) {
            u32 a = smb + AOF_VH + vrow + dg*32 + chi;
            u32 vfh[4];
            ldsm4t(vfh, a);
            mma16816h(cU[2*dg],   Af, vfh[0], vfh[1]);
            mma16816h(cU[2*dg+1], Af, vfh[2], vfh[3]);
          }
        }
      }
    }

    float t0 = rs0;
    t0 += __shfl_xor_sync(0xFFFFFFFFu, t0, 1);
    t0 += __shfl_xor_sync(0xFFFFFFFFu, t0, 2);
    float t1 = rs1;
    t1 += __shfl_xor_sync(0xFFFFFFFFu, t1, 1);
    t1 += __shfl_xor_sync(0xFFFFFFFFu, t1, 2);
    const float r0 = rcpf(t0), r1 = rcpf(t1);
    #pragma unroll
    for (int i = 0; i < 8; i++) {
      ctxa[i][0] += cU[i][0] * r0;
      ctxa[i][1] += cU[i][1] * r0;
      ctxa[i][2] += cU[i][2] * r1;
      ctxa[i][3] += cU[i][3] * r1;
    }
  }

  {
    const int row0 = n0 + w*16 + gr;
    const size_t base0 = ((size_t)b*SEQ + row0) * FD + h*DH;
    const size_t base1 = base0 + (size_t)8 * FD;
    #pragma unroll
    for (int nt = 0; nt < 8; nt++) {
      const int cc = nt*8 + 2*tg;
      u32 hw, lw;
      tsplit2(ctxa[nt][0], ctxa[nt][1], hw, lw);
      *(u32*)&ctxh[base0 + cc] = hw;
      *(u32*)&ctxl[base0 + cc] = lw;
      tsplit2(ctxa[nt][2], ctxa[nt][3], hw, lw);
      *(u32*)&ctxh[base1 + cc] = hw;
      *(u32*)&ctxl[base1 + cc] = lw;
    }
  }
}

// ---------------- launch ----------------
extern "C" void kernel_launch(void* const* d_in, const int* in_sizes, int n_in,
                              void* d_out, int out_size) {
  (void)in_sizes; (void)n_in; (void)out_size;
  const float* x     = (const float*)d_in[0];
  const int*   adj   = (const int*)  d_in[1];
  const float* Wq    = (const float*)d_in[2];
  const float* bq    = (const float*)d_in[3];
  const float* Wk    = (const float*)d_in[4];
  const float* bk    = (const float*)d_in[5];
  const float* Wv    = (const float*)d_in[6];
  const float* bv    = (const float*)d_in[7];
  const float* Wo    = (const float*)d_in[8];
  const float* bo    = (const float*)d_in[9];
  const float* gamma = (const float*)d_in[10];
  const float* beta  = (const float*)d_in[11];
  float* out = (float*)d_out;

  __nv_bfloat16 *pxh, *pxl, *pxf, *pqf, *pkh, *pkl, *pvh, *pch, *pcl;
  __nv_bfloat16 *pwqh, *pwql, *pwkh, *pwkl, *pwvh, *pwvl, *pwoh, *pwol;
  unsigned* padjb;
  cudaGetSymbolAddress((void**)&pxh, g_xh);
  cudaGetSymbolAddress((void**)&pxl, g_xl);
  cudaGetSymbolAddress((void**)&pxf, g_xf);
  cudaGetSymbolAddress((void**)&pqf, g_qf);
  cudaGetSymbolAddress((void**)&pkh, g_kh);
  cudaGetSymbolAddress((void**)&pkl, g_kl);
  cudaGetSymbolAddress((void**)&pvh, g_vh);
  cudaGetSymbolAddress((void**)&pch, g_ch);
  cudaGetSymbolAddress((void**)&pcl, g_cl);
  cudaGetSymbolAddress((void**)&pwqh, g_wqh);
  cudaGetSymbolAddress((void**)&pwql, g_wql);
  cudaGetSymbolAddress((void**)&pwkh, g_wkh);
  cudaGetSymbolAddress((void**)&pwkl, g_wkl);
  cudaGetSymbolAddress((void**)&pwvh, g_wvh);
  cudaGetSymbolAddress((void**)&pwvl, g_wvl);
  cudaGetSymbolAddress((void**)&pwoh, g_woh);
  cudaGetSymbolAddress((void**)&pwol, g_wol);
  cudaGetSymbolAddress((void**)&padjb, g_adjb);

  const float QS = 0.18033688011112042f;   // 0.125 * log2(e)

  prep_kernel<<<3072, 256>>>(adj, padjb, x, pxh, pxl, pxf,
      Wq, Wk, Wv, Wo,
      pwqh, pwql, pwkh, pwkl, pwvh, pwvl, pwoh, pwol, QS);

  cudaFuncSetAttribute(qkv_hmma_kernel, cudaFuncAttributeMaxDynamicSharedMemorySize,
                       GEMM_SMEM);
  qkv_hmma_kernel<<<dim3((BATCH*SEQ)/64, 6), 128, GEMM_SMEM>>>(
      pxh, pxl, pxf, pwqh, pwql, pwkh, pwkl, pwvh, pwvl, bq, bk, bv,
      pqf, pkh, pkl, pvh, QS);

  cudaFuncSetAttribute(attn_hmma_kernel, cudaFuncAttributeMaxDynamicSharedMemorySize,
                       SM_ATTN);
  const dim3 ga(SEQ / 64, NH, BATCH);
  attn_hmma_kernel<<<ga, 128, SM_ATTN>>>(pqf, pkh, pkl, pvh, padjb, pch, pcl);

  cudaFuncSetAttribute(o_ln_kernel, cudaFuncAttributeMaxDynamicSharedMemorySize,
                       O_SMEM);
  o_ln_kernel<<<(BATCH*SEQ)/64, 128, O_SMEM>>>(
      pch, pcl, pwoh, pwol, bo, x, gamma, beta, out);
}

// round 17
// speedup vs baseline: 1.1167x; 1.1167x over previous
#include <cuda_runtime.h>
#include <cuda_bf16.h>
#include <cuda_fp16.h>
#include <cstdint>

#define BATCH 4
#define SEQ   2048
#define FD    256
#define NH    4
#define DH    64
#define CHK   256
#define NCHUNK 8

typedef unsigned long long ull;
typedef uint32_t u32;

// ---------------- device scratch ----------------
__device__ __nv_bfloat16 g_xh[BATCH*SEQ*FD];   // bf16 hi (K path)
__device__ __nv_bfloat16 g_xl[BATCH*SEQ*FD];   // bf16 lo (K path)
__device__ __nv_bfloat16 g_xf[BATCH*SEQ*FD];   // fp16 single (Q/V path)
__device__ __nv_bfloat16 g_qf[BATCH*SEQ*FD];   // fp16 single
__device__ __nv_bfloat16 g_kh[BATCH*SEQ*FD];   // fp16 hi
__device__ __nv_bfloat16 g_kl[BATCH*SEQ*FD];   // fp16 lo
__device__ __nv_bfloat16 g_vh[BATCH*SEQ*FD];   // fp16 single
__device__ __nv_bfloat16 g_ch[BATCH*SEQ*FD];   // ctx bf16 hi
__device__ __nv_bfloat16 g_cl[BATCH*SEQ*FD];   // ctx bf16 lo
__device__ __nv_bfloat16 g_wqh[FD*FD], g_wql[FD*FD];   // fp16 hi/lo (scaled)
__device__ __nv_bfloat16 g_wkh[FD*FD], g_wkl[FD*FD];   // bf16 hi/lo
__device__ __nv_bfloat16 g_wvh[FD*FD], g_wvl[FD*FD];   // fp16 hi/lo
__device__ __nv_bfloat16 g_woh[FD*FD], g_wol[FD*FD];   // bf16 hi/lo
__device__ unsigned g_adjb[SEQ * (SEQ/32)];

// ---------------- helpers ----------------
__device__ __forceinline__ u32 smem_u32(const void* p) {
  u32 a; asm("{ .reg .u64 t; cvta.to.shared.u64 t, %1; cvt.u32.u64 %0, t; }"
             : "=r"(a) : "l"(p)); return a;
}
__device__ __forceinline__ float ex2f(float x) {
  float r; asm("ex2.approx.f32 %0, %1;" : "=f"(r) : "f"(x)); return r;
}
__device__ __forceinline__ float rcpf(float x) {
  float r; asm("rcp.approx.f32 %0, %1;" : "=f"(r) : "f"(x)); return r;
}
__device__ __forceinline__ void tsplit2(float x0, float x1, u32& hw, u32& lw) {
  u32 b0 = __float_as_uint(x0), b1 = __float_as_uint(x1);
  u32 h0 = b0 & 0xFFFF0000u, h1 = b1 & 0xFFFF0000u;
  hw = (b0 >> 16) | h1;
  float l0 = x0 - __uint_as_float(h0);
  float l1 = x1 - __uint_as_float(h1);
  asm("cvt.rn.bf16x2.f32 %0, %1, %2;" : "=r"(lw) : "f"(l1), "f"(l0));
}
__device__ __forceinline__ void hsplit2(float x0, float x1, u32& hw, u32& lw) {
  u32 h;
  asm("cvt.rn.f16x2.f32 %0, %1, %2;" : "=r"(h) : "f"(x1), "f"(x0));
  __half2 hh = *reinterpret_cast<__half2*>(&h);
  float r0 = x0 - __low2float(hh);
  float r1 = x1 - __high2float(hh);
  hw = h;
  asm("cvt.rn.f16x2.f32 %0, %1, %2;" : "=r"(lw) : "f"(r1), "f"(r0));
}
__device__ __forceinline__ u32 hpack2(float x0, float x1) {
  u32 h;
  asm("cvt.rn.f16x2.f32 %0, %1, %2;" : "=r"(h) : "f"(x1), "f"(x0));
  return h;
}
__device__ __forceinline__ void ldsm4(u32* r, u32 addr) {
  asm volatile("ldmatrix.sync.aligned.m8n8.x4.shared.b16 {%0,%1,%2,%3}, [%4];"
    : "=r"(r[0]), "=r"(r[1]), "=r"(r[2]), "=r"(r[3]) : "r"(addr));
}
__device__ __forceinline__ void ldsm4t(u32* r, u32 addr) {
  asm volatile("ldmatrix.sync.aligned.m8n8.x4.trans.shared.b16 {%0,%1,%2,%3}, [%4];"
    : "=r"(r[0]), "=r"(r[1]), "=r"(r[2]), "=r"(r[3]) : "r"(addr));
}
__device__ __forceinline__ void mma16816(float* d, const u32* a, u32 b0, u32 b1) {
  asm volatile("mma.sync.aligned.m16n8k16.row.col.f32.bf16.bf16.f32 "
    "{%0,%1,%2,%3}, {%4,%5,%6,%7}, {%8,%9}, {%0,%1,%2,%3};"
    : "+f"(d[0]), "+f"(d[1]), "+f"(d[2]), "+f"(d[3])
    : "r"(a[0]), "r"(a[1]), "r"(a[2]), "r"(a[3]), "r"(b0), "r"(b1));
}
__device__ __forceinline__ void mma16816h(float* d, const u32* a, u32 b0, u32 b1) {
  asm volatile("mma.sync.aligned.m16n8k16.row.col.f32.f16.f16.f32 "
    "{%0,%1,%2,%3}, {%4,%5,%6,%7}, {%8,%9}, {%0,%1,%2,%3};"
    : "+f"(d[0]), "+f"(d[1]), "+f"(d[2]), "+f"(d[3])
    : "r"(a[0]), "r"(a[1]), "r"(a[2]), "r"(a[3]), "r"(b0), "r"(b1));
}
#define CPA16(dst, src) \
  asm volatile("cp.async.cg.shared.global [%0], [%1], 16;" \
               :: "r"(dst), "l"(src) : "memory")
#define CPA_FENCE() do { \
  asm volatile("cp.async.commit_group;" ::: "memory"); \
  asm volatile("cp.async.wait_group 0;" ::: "memory"); \
} while (0)

// ---------------- fused prep ----------------
__global__ void prep_kernel(
    const int* __restrict__ adj, unsigned* __restrict__ adjb,
    const float* __restrict__ x,
    __nv_bfloat16* __restrict__ xh, __nv_bfloat16* __restrict__ xl,
    __nv_bfloat16* __restrict__ xf,
    const float* __restrict__ Wq, const float* __restrict__ Wk,
    const float* __restrict__ Wv, const float* __restrict__ Wo,
    __nv_bfloat16* __restrict__ wqh, __nv_bfloat16* __restrict__ wql,
    __nv_bfloat16* __restrict__ wkh, __nv_bfloat16* __restrict__ wkl,
    __nv_bfloat16* __restrict__ wvh, __nv_bfloat16* __restrict__ wvl,
    __nv_bfloat16* __restrict__ woh, __nv_bfloat16* __restrict__ wol,
    float qs) {
  const int bx = blockIdx.x;
  const int t = threadIdx.x;
  if (bx < 512) {
    const int idx = bx * 256 + t;
    const int4* p = (const int4*)(adj + (size_t)idx * 32);
    unsigned b = 0;
    #pragma unroll
    for (int u = 0; u < 8; u++) {
      int4 v = p[u];
      b |= (v.x != 0 ? 1u : 0u) << (u*4 + 0);
      b |= (v.y != 0 ? 1u : 0u) << (u*4 + 1);
      b |= (v.z != 0 ? 1u : 0u) << (u*4 + 2);
      b |= (v.w != 0 ? 1u : 0u) << (u*4 + 3);
    }
    adjb[idx] = b;
  } else if (bx < 2560) {
    const int i = ((bx - 512) * 256 + t) * 4;
    float4 v = *(const float4*)&x[i];
    u32 h0, l0, h1, l1;
    tsplit2(v.x, v.y, h0, l0);
    tsplit2(v.z, v.w, h1, l1);
    *(u32*)&xh[i]   = h0; *(u32*)&xh[i+2] = h1;
    *(u32*)&xl[i]   = l0; *(u32*)&xl[i+2] = l1;
    *(u32*)&xf[i]   = hpack2(v.x, v.y);
    *(u32*)&xf[i+2] = hpack2(v.z, v.w);
  } else {
    const int bw = bx - 2560;
    const int m = bw >> 7;
    const int i = ((bw & 127) * 256 + t) * 2;
    const float* src = (m == 0) ? Wq : (m == 1) ? Wk : (m == 2) ? Wv : Wo;
    __nv_bfloat16* dh = (m == 0) ? wqh : (m == 1) ? wkh : (m == 2) ? wvh : woh;
    __nv_bfloat16* dl = (m == 0) ? wql : (m == 1) ? wkl : (m == 2) ? wvl : wol;
    const float s = (m == 0) ? qs : 1.f;
    float2 v = *(const float2*)&src[i];
    u32 hw, lw;
    if (m == 0 || m == 2) hsplit2(v.x * s, v.y * s, hw, lw);
    else                  tsplit2(v.x, v.y, hw, lw);
    *(u32*)&dh[i] = hw;
    *(u32*)&dl[i] = lw;
  }
}

// ---------------- QKV HMMA GEMM: 64x128 tile, 128 threads ----------------
#define GP 144
#define GOF_AH 0
#define GOF_AL 9216
#define GOF_WH 18432
#define GOF_WL 36864
#define GEMM_SMEM 55296

__global__ void __launch_bounds__(128, 3) qkv_hmma_kernel(
    const __nv_bfloat16* __restrict__ xh, const __nv_bfloat16* __restrict__ xl,
    const __nv_bfloat16* __restrict__ xf,
    const __nv_bfloat16* __restrict__ wqh, const __nv_bfloat16* __restrict__ wql,
    const __nv_bfloat16* __restrict__ wkh, const __nv_bfloat16* __restrict__ wkl,
    const __nv_bfloat16* __restrict__ wvh, const __nv_bfloat16* __restrict__ wvl,
    const float* __restrict__ bq, const float* __restrict__ bk,
    const float* __restrict__ bv,
    __nv_bfloat16* __restrict__ qf,
    __nv_bfloat16* __restrict__ kh, __nv_bfloat16* __restrict__ kl,
    __nv_bfloat16* __restrict__ vh,
    float qs) {
  extern __shared__ __align__(16) char smem[];
  const int p = blockIdx.y >> 1, half = blockIdx.y & 1;
  const bool kpath = (p == 1);
  const __nv_bfloat16* Wh = (p == 0) ? wqh : (p == 1) ? wkh : wvh;
  const __nv_bfloat16* Wl = (p == 0) ? wql : (p == 1) ? wkl : wvl;
  const float* bias = (p == 0) ? bq : (p == 1) ? bk : bv;
  __nv_bfloat16* Ch = (p == 0) ? qf : (p == 1) ? kh : vh;
  const float sb = (p == 0) ? qs : 1.f;
  const int m0 = blockIdx.x * 64, n0g = half * 128;

  const u32 smb = smem_u32(smem);
  const int t = threadIdx.x;
  const int w = t >> 5, l = t & 31;
  const int gr = l >> 2, tg = l & 3;

  float acc[16][4];
  #pragma unroll
  for (int nt = 0; nt < 16; nt++)
    #pragma unroll
    for (int d = 0; d < 4; d++) acc[nt][d] = 0.f;

  for (int kc = 0; kc < 4; kc++) {
    const int k0 = kc * 64;
    __syncthreads();
    if (kpath) {
      #pragma unroll
      for (int i = 0; i < 4; i++) {
        int idx = t + i * 128;
        int r = idx >> 3, c = idx & 7;
        u32 so = r * GP + c * 16;
        size_t ga = ((size_t)(m0 + r) * FD + k0) * 2 + c * 16;
        CPA16(smb + GOF_AH + so, (const char*)xh + ga);
        CPA16(smb + GOF_AL + so, (const char*)xl + ga);
      }
    } else {
      #pragma unroll
      for (int i = 0; i < 4; i++) {
        int idx = t + i * 128;
        int r = idx >> 3, c = idx & 7;
        u32 so = r * GP + c * 16;
        size_t ga = ((size_t)(m0 + r) * FD + k0) * 2 + c * 16;
        CPA16(smb + GOF_AH + so, (const char*)xf + ga);
      }
    }
    #pragma unroll
    for (int i = 0; i < 8; i++) {
      int idx = t + i * 128;
      int r = idx >> 3, c = idx & 7;
      u32 so = r * GP + c * 16;
      size_t gw = ((size_t)(n0g + r) * FD + k0) * 2 + c * 16;
      CPA16(smb + GOF_WH + so, (const char*)Wh + gw);
      CPA16(smb + GOF_WL + so, (const char*)Wl + gw);
    }
    CPA_FENCE();
    __syncthreads();

    const u32 lrow = (u32)(l & 15) * GP;
    const u32 chi  = (u32)(l >> 4) * 16;
    if (kpath) {
      #pragma unroll
      for (int ks = 0; ks < 4; ks++) {
        u32 aa = smb + GOF_AH + (u32)(w * 16) * GP + lrow + ks * 32 + chi;
        u32 ah[4], al2[4];
        ldsm4(ah, aa);
        ldsm4(al2, aa + (GOF_AL - GOF_AH));
        #pragma unroll
        for (int g = 0; g < 8; g++) {
          u32 wa = smb + GOF_WH + (u32)(g * 16) * GP + lrow + ks * 32 + chi;
          u32 bh[4], bl[4];
          ldsm4(bh, wa);
          ldsm4(bl, wa + (GOF_WL - GOF_WH));
          mma16816(acc[2*g],   ah,  bh[0], bh[2]);
          mma16816(acc[2*g+1], ah,  bh[1], bh[3]);
          mma16816(acc[2*g],   ah,  bl[0], bl[2]);
          mma16816(acc[2*g+1], ah,  bl[1], bl[3]);
          mma16816(acc[2*g],   al2, bh[0], bh[2]);
          mma16816(acc[2*g+1], al2, bh[1], bh[3]);
        }
      }
    } else {
      #pragma unroll
      for (int ks = 0; ks < 4; ks++) {
        u32 aa = smb + GOF_AH + (u32)(w * 16) * GP + lrow + ks * 32 + chi;
        u32 af[4];
        ldsm4(af, aa);
        #pragma unroll
        for (int g = 0; g < 8; g++) {
          u32 wa = smb + GOF_WH + (u32)(g * 16) * GP + lrow + ks * 32 + chi;
          u32 bh[4], bl[4];
          ldsm4(bh, wa);
          ldsm4(bl, wa + (GOF_WL - GOF_WH));
          mma16816h(acc[2*g],   af, bh[0], bh[2]);
          mma16816h(acc[2*g+1], af, bh[1], bh[3]);
          mma16816h(acc[2*g],   af, bl[0], bl[2]);
          mma16816h(acc[2*g+1], af, bl[1], bl[3]);
        }
      }
    }
  }

  const int mrow = m0 + w * 16 + gr;
  #pragma unroll
  for (int nt = 0; nt < 16; nt++) {
    const int n = n0g + nt * 8 + 2 * tg;
    const float bx = bias[n] * sb, by = bias[n + 1] * sb;
    float c00 = acc[nt][0] + bx, c01 = acc[nt][1] + by;
    float c10 = acc[nt][2] + bx, c11 = acc[nt][3] + by;
    if (kpath) {
      u32 hw, lw;
      hsplit2(c00, c01, hw, lw);
      *(u32*)&kh[(size_t)mrow * FD + n] = hw;
      *(u32*)&kl[(size_t)mrow * FD + n] = lw;
      hsplit2(c10, c11, hw, lw);
      *(u32*)&kh[(size_t)(mrow + 8) * FD + n] = hw;
      *(u32*)&kl[(size_t)(mrow + 8) * FD + n] = lw;
    } else {
      *(u32*)&Ch[(size_t)mrow * FD + n]       = hpack2(c00, c01);
      *(u32*)&Ch[(size_t)(mrow + 8) * FD + n] = hpack2(c10, c11);
    }
  }
}

// ---------------- Fused O-projection + residual + LayerNorm ----------------
// 64x256 tile, 256 threads (8 warps): warp = (row-group rg = w&3, col-half ch = w>>2).
#define OO_AH 0
#define OO_AL 9216
#define OO_WH 18432
#define OO_WL (18432 + 36864)
#define O_SMEM (18432 + 2*36864)   // 92160

__global__ void __launch_bounds__(256, 2) o_ln_kernel(
    const __nv_bfloat16* __restrict__ ch_, const __nv_bfloat16* __restrict__ cl_,
    const __nv_bfloat16* __restrict__ woh, const __nv_bfloat16* __restrict__ wol,
    const float* __restrict__ bo, const float* __restrict__ x,
    const float* __restrict__ gamma, const float* __restrict__ beta,
    float* __restrict__ out) {
  extern __shared__ __align__(16) char smem[];
  const u32 smb = smem_u32(smem);
  const int m0 = blockIdx.x * 64;
  const int t = threadIdx.x;
  const int w = t >> 5, l = t & 31;
  const int rg = w & 3, chf = w >> 2;
  const int gr = l >> 2, tg = l & 3;

  float acc[16][4];
  #pragma unroll
  for (int nt = 0; nt < 16; nt++)
    #pragma unroll
    for (int d = 0; d < 4; d++) acc[nt][d] = 0.f;

  for (int kc = 0; kc < 4; kc++) {
    const int k0 = kc * 64;
    __syncthreads();
    #pragma unroll
    for (int i = 0; i < 2; i++) {
      int idx = t + i * 256;
      int r = idx >> 3, c = idx & 7;
      u32 so = r * GP + c * 16;
      size_t ga = ((size_t)(m0 + r) * FD + k0) * 2 + c * 16;
      CPA16(smb + OO_AH + so, (const char*)ch_ + ga);
      CPA16(smb + OO_AL + so, (const char*)cl_ + ga);
    }
    #pragma unroll
    for (int i = 0; i < 8; i++) {
      int idx = t + i * 256;
      int r = idx >> 3, c = idx & 7;
      u32 so = r * GP + c * 16;
      size_t gw = ((size_t)r * FD + k0) * 2 + c * 16;
      CPA16(smb + OO_WH + so, (const char*)woh + gw);
      CPA16(smb + OO_WL + so, (const char*)wol + gw);
    }
    CPA_FENCE();
    __syncthreads();

    const u32 lrow = (u32)(l & 15) * GP;
    const u32 chi  = (u32)(l >> 4) * 16;
    #pragma unroll
    for (int ks = 0; ks < 4; ks++) {
      u32 aa = smb + OO_AH + (u32)(rg * 16) * GP + lrow + ks * 32 + chi;
      u32 ah[4], al2[4];
      ldsm4(ah, aa);
      ldsm4(al2, aa + (OO_AL - OO_AH));
      #pragma unroll
      for (int g = 0; g < 8; g++) {
        u32 wa = smb + OO_WH + (u32)((chf * 8 + g) * 16) * GP + lrow + ks * 32 + chi;
        u32 bh[4], bl[4];
        ldsm4(bh, wa);
        ldsm4(bl, wa + (OO_WL - OO_WH));
        mma16816(acc[2*g],   ah,  bh[0], bh[2]);
        mma16816(acc[2*g+1], ah,  bh[1], bh[3]);
        mma16816(acc[2*g],   ah,  bl[0], bl[2]);
        mma16816(acc[2*g+1], ah,  bl[1], bl[3]);
        mma16816(acc[2*g],   al2, bh[0], bh[2]);
        mma16816(acc[2*g+1], al2, bh[1], bh[3]);
      }
    }
  }

  // epilogue: bias + resid, per-half partial LN sums
  const int rl0 = rg * 16 + gr;        // local row
  const int rl1 = rl0 + 8;
  const int r0 = m0 + rl0, r1 = m0 + rl1;
  const int nb = chf * 128;
  float s1a = 0.f, s2a = 0.f, s1b = 0.f, s2b = 0.f;
  #pragma unroll
  for (int nt = 0; nt < 16; nt++) {
    const int n = nb + nt * 8 + 2 * tg;
    const float2 bb = *(const float2*)&bo[n];
    const float2 x0 = *(const float2*)&x[(size_t)r0 * FD + n];
    const float2 x1 = *(const float2*)&x[(size_t)r1 * FD + n];
    acc[nt][0] += bb.x + x0.x;
    acc[nt][1] += bb.y + x0.y;
    acc[nt][2] += bb.x + x1.x;
    acc[nt][3] += bb.y + x1.y;
    s1a += acc[nt][0] + acc[nt][1];
    s2a += acc[nt][0]*acc[nt][0] + acc[nt][1]*acc[nt][1];
    s1b += acc[nt][2] + acc[nt][3];
    s2b += acc[nt][2]*acc[nt][2] + acc[nt][3]*acc[nt][3];
  }
  #pragma unroll
  for (int off = 1; off <= 2; off <<= 1) {
    s1a += __shfl_xor_sync(0xFFFFFFFFu, s1a, off);
    s2a += __shfl_xor_sync(0xFFFFFFFFu, s2a, off);
    s1b += __shfl_xor_sync(0xFFFFFFFFu, s1b, off);
    s2b += __shfl_xor_sync(0xFFFFFFFFu, s2b, off);
  }

  // cross-half combine via smem: red[row][half][2]
  float* red = (float*)smem;           // 64*2*2 = 256 floats, staging is dead
  __syncthreads();
  if (tg == 0) {
    red[(rl0 * 2 + chf) * 2 + 0] = s1a;
    red[(rl0 * 2 + chf) * 2 + 1] = s2a;
    red[(rl1 * 2 + chf) * 2 + 0] = s1b;
    red[(rl1 * 2 + chf) * 2 + 1] = s2b;
  }
  __syncthreads();
  const float S1a = red[(rl0*2+0)*2+0] + red[(rl0*2+1)*2+0];
  const float S2a = red[(rl0*2+0)*2+1] + red[(rl0*2+1)*2+1];
  const float S1b = red[(rl1*2+0)*2+0] + red[(rl1*2+1)*2+0];
  const float S2b = red[(rl1*2+0)*2+1] + red[(rl1*2+1)*2+1];
  const float mua = S1a * (1.f / FD);
  const float mub = S1b * (1.f / FD);
  const float ra = rsqrtf(S2a * (1.f / FD) - mua * mua + 1e-5f);
  const float rb = rsqrtf(S2b * (1.f / FD) - mub * mub + 1e-5f);

  #pragma unroll
  for (int nt = 0; nt < 16; nt++) {
    const int n = nb + nt * 8 + 2 * tg;
    const float2 gg = *(const float2*)&gamma[n];
    const float2 be = *(const float2*)&beta[n];
    float2 o0, o1;
    o0.x = (acc[nt][0] - mua) * ra * gg.x + be.x;
    o0.y = (acc[nt][1] - mua) * ra * gg.y + be.y;
    o1.x = (acc[nt][2] - mub) * rb * gg.x + be.x;
    o1.y = (acc[nt][3] - mub) * rb * gg.y + be.y;
    *(float2*)&out[(size_t)r0 * FD + n] = o0;
    *(float2*)&out[(size_t)r1 * FD + n] = o1;
  }
}

// ---------------- HMMA attention: fp16 S (Qf x Khi/Klo) + fp16 PV ----------
#define AP 144
#define AOF_Q  0
#define AOF_KH 9216
#define AOF_KL (AOF_KH + 18432)
#define AOF_VH (AOF_KL + 18432)
#define AOF_ADJ (AOF_VH + 18432)      // 64512
#define SM_ATTN (AOF_ADJ + 2048)      // 66560

__global__ void __launch_bounds__(128, 2) attn_hmma_kernel(
    const __nv_bfloat16* __restrict__ qf,
    const __nv_bfloat16* __restrict__ kh, const __nv_bfloat16* __restrict__ kl,
    const __nv_bfloat16* __restrict__ vh,
    const unsigned* __restrict__ adjb,
    __nv_bfloat16* __restrict__ ctxh, __nv_bfloat16* __restrict__ ctxl) {
  extern __shared__ __align__(16) char smem[];
  const u32 smb = smem_u32(smem);
  unsigned* adj_s = (unsigned*)(smem + AOF_ADJ);

  const int b  = blockIdx.z;
  const int h  = blockIdx.y;
  const int n0 = blockIdx.x * 64;
  const int t  = threadIdx.x;
  const int w  = t >> 5;
  const int l  = t & 31;
  const int gr = l >> 2, tg = l & 3;

  const float CLIP = 14.426950408889634f;
  const float ENEG = 4.5399929762484854e-05f;

  {
    const char* gq = (const char*)(qf + ((size_t)b*SEQ + n0)*FD + h*DH);
    #pragma unroll
    for (int i = 0; i < 4; i++) {
      int idx = t + i * 128;
      int r = idx >> 3, c = idx & 7;
      CPA16(smb + AOF_Q + r * AP + c * 16, gq + (size_t)r*512 + c*16);
    }
    CPA_FENCE();
  }
  __syncthreads();

  u32 qfr[4][4];
  {
    const u32 rowoff = (u32)(w*16 + (l & 15)) * AP;
    const u32 coloff = (u32)((l >> 4) * 8) * 2;
    #pragma unroll
    for (int ks = 0; ks < 4; ks++)
      ldsm4(qfr[ks], smb + AOF_Q + rowoff + ks*32 + coloff);
  }

  float ctxa[8][4];
  #pragma unroll
  for (int i = 0; i < 8; i++)
    #pragma unroll
    for (int d = 0; d < 4; d++) ctxa[i][d] = 0.f;

  const char* gkh = (const char*)(kh + ((size_t)b*SEQ)*FD + h*DH);
  const char* gkl = (const char*)(kl + ((size_t)b*SEQ)*FD + h*DH);
  const char* gvh = (const char*)(vh + ((size_t)b*SEQ)*FD + h*DH);

  const int lr0 = w*16 + gr;

  for (int j = 0; j < NCHUNK; ++j) {
    __syncthreads();

    #pragma unroll
    for (int i = 0; i < 4; i++) {
      int idx = t + i * 128;
      int row = idx >> 3, wi = idx & 7;
      adj_s[idx] = adjb[(size_t)(n0 + row) * (SEQ/32) + j * 8 + wi];
    }

    float rs0 = 0.f, rs1 = 0.f;
    float cU[8][4];
    #pragma unroll
    for (int i = 0; i < 8; i++)
      #pragma unroll
      for (int d = 0; d < 4; d++) cU[i][d] = 0.f;

    for (int hf = 0; hf < 2; hf++) {
      if (hf) __syncthreads();
      {
        const size_t gb = (size_t)(j * CHK + hf * 128) * 512;
        #pragma unroll
        for (int i = 0; i < 8; i++) {
          int idx = t + i * 128;
          int r = idx >> 3, c = idx & 7;
          size_t go = gb + (size_t)r*512 + c*16;
          u32 so = r * AP + c * 16;
          CPA16(smb + AOF_KH + so, gkh + go);
          CPA16(smb + AOF_KL + so, gkl + go);
          CPA16(smb + AOF_VH + so, gvh + go);
        }
        CPA_FENCE();
      }
      __syncthreads();

      #pragma unroll
      for (int kb = 0; kb < 2; kb++) {
        const int key0 = kb * 64;
        float S[8][4];
        #pragma unroll
        for (int i = 0; i < 8; i++)
          #pragma unroll
          for (int d = 0; d < 4; d++) S[i][d] = 0.f;

        const u32 lrow16 = (u32)(l & 15) * AP;
        const u32 chi = (u32)((l >> 4) * 8) * 2;
        #pragma unroll
        for (int ks = 0; ks < 4; ks++) {
          #pragma unroll
          for (int g = 0; g < 4; g++) {
            u32 a = smb + AOF_KH + (u32)(key0 + g*16)*AP + lrow16 + ks*32 + chi;
            u32 kf[4], kf2[4];
            ldsm4(kf,  a);
            ldsm4(kf2, a + (AOF_KL - AOF_KH));
            mma16816h(S[2*g],   qfr[ks], kf[0],  kf[2]);
            mma16816h(S[2*g+1], qfr[ks], kf[1],  kf[3]);
            mma16816h(S[2*g],   qfr[ks], kf2[0], kf2[2]);
            mma16816h(S[2*g+1], qfr[ks], kf2[1], kf2[3]);
          }
        }

        const int wbase = lr0*8 + hf*4 + kb*2;
        const u32 w00 = adj_s[wbase + 0];
        const u32 w01 = adj_s[wbase + 1];
        const u32 w10 = adj_s[wbase + 64 + 0];
        const u32 w11 = adj_s[wbase + 64 + 1];
        u32 Pf0[8], Pf1[8];
        #pragma unroll
        for (int nt = 0; nt < 8; nt++) {
          const u32 a0w = (nt < 4) ? w00 : w01;
          const u32 a1w = (nt < 4) ? w10 : w11;
          const int bit = (nt & 3) * 8 + 2 * tg;
          float x;
          x = fminf(fmaxf(S[nt][0], -CLIP), CLIP);
          float e00 = ((a0w >> bit) & 1u)     ? ex2f(x) : ENEG;
          x = fminf(fmaxf(S[nt][1], -CLIP), CLIP);
          float e01 = ((a0w >> (bit+1)) & 1u) ? ex2f(x) : ENEG;
          x = fminf(fmaxf(S[nt][2], -CLIP), CLIP);
          float e10 = ((a1w >> bit) & 1u)     ? ex2f(x) : ENEG;
          x = fminf(fmaxf(S[nt][3], -CLIP), CLIP);
          float e11 = ((a1w >> (bit+1)) & 1u) ? ex2f(x) : ENEG;
          rs0 += e00 + e01;
          rs1 += e10 + e11;
          Pf0[nt] = hpack2(e00, e01);
          Pf1[nt] = hpack2(e10, e11);
        }

        #pragma unroll
        for (int kt = 0; kt < 4; kt++) {
          u32 Af[4] = { Pf0[2*kt], Pf1[2*kt], Pf0[2*kt+1], Pf1[2*kt+1] };
          const u32 vrow = (u32)(key0 + kt*16) * AP + lrow16;
          #pragma unroll
          for (int dg = 0; dg < 4; dg++) {
            u32 a = smb + AOF_VH + vrow + dg*32 + chi;
            u32 vfh[4];
            ldsm4t(vfh, a);
            mma16816h(cU[2*dg],   Af, vfh[0], vfh[1]);
            mma16816h(cU[2*dg+1], Af, vfh[2], vfh[3]);
          }
        }
      }
    }

    float t0 = rs0;
    t0 += __shfl_xor_sync(0xFFFFFFFFu, t0, 1);
    t0 += __shfl_xor_sync(0xFFFFFFFFu, t0, 2);
    float t1 = rs1;
    t1 += __shfl_xor_sync(0xFFFFFFFFu, t1, 1);
    t1 += __shfl_xor_sync(0xFFFFFFFFu, t1, 2);
    const float r0 = rcpf(t0), r1 = rcpf(t1);
    #pragma unroll
    for (int i = 0; i < 8; i++) {
      ctxa[i][0] += cU[i][0] * r0;
      ctxa[i][1] += cU[i][1] * r0;
      ctxa[i][2] += cU[i][2] * r1;
      ctxa[i][3] += cU[i][3] * r1;
    }
  }

  {
    const int row0 = n0 + w*16 + gr;
    const size_t base0 = ((size_t)b*SEQ + row0) * FD + h*DH;
    const size_t base1 = base0 + (size_t)8 * FD;
    #pragma unroll
    for (int nt = 0; nt < 8; nt++) {
      const int cc = nt*8 + 2*tg;
      u32 hw, lw;
      tsplit2(ctxa[nt][0], ctxa[nt][1], hw, lw);
      *(u32*)&ctxh[base0 + cc] = hw;
      *(u32*)&ctxl[base0 + cc] = lw;
      tsplit2(ctxa[nt][2], ctxa[nt][3], hw, lw);
      *(u32*)&ctxh[base1 + cc] = hw;
      *(u32*)&ctxl[base1 + cc] = lw;
    }
  }
}

// ---------------- launch ----------------
extern "C" void kernel_launch(void* const* d_in, const int* in_sizes, int n_in,
                              void* d_out, int out_size) {
  (void)in_sizes; (void)n_in; (void)out_size;
  const float* x     = (const float*)d_in[0];
  const int*   adj   = (const int*)  d_in[1];
  const float* Wq    = (const float*)d_in[2];
  const float* bq    = (const float*)d_in[3];
  const float* Wk    = (const float*)d_in[4];
  const float* bk    = (const float*)d_in[5];
  const float* Wv    = (const float*)d_in[6];
  const float* bv    = (const float*)d_in[7];
  const float* Wo    = (const float*)d_in[8];
  const float* bo    = (const float*)d_in[9];
  const float* gamma = (const float*)d_in[10];
  const float* beta  = (const float*)d_in[11];
  float* out = (float*)d_out;

  __nv_bfloat16 *pxh, *pxl, *pxf, *pqf, *pkh, *pkl, *pvh, *pch, *pcl;
  __nv_bfloat16 *pwqh, *pwql, *pwkh, *pwkl, *pwvh, *pwvl, *pwoh, *pwol;
  unsigned* padjb;
  cudaGetSymbolAddress((void**)&pxh, g_xh);
  cudaGetSymbolAddress((void**)&pxl, g_xl);
  cudaGetSymbolAddress((void**)&pxf, g_xf);
  cudaGetSymbolAddress((void**)&pqf, g_qf);
  cudaGetSymbolAddress((void**)&pkh, g_kh);
  cudaGetSymbolAddress((void**)&pkl, g_kl);
  cudaGetSymbolAddress((void**)&pvh, g_vh);
  cudaGetSymbolAddress((void**)&pch, g_ch);
  cudaGetSymbolAddress((void**)&pcl, g_cl);
  cudaGetSymbolAddress((void**)&pwqh, g_wqh);
  cudaGetSymbolAddress((void**)&pwql, g_wql);
  cudaGetSymbolAddress((void**)&pwkh, g_wkh);
  cudaGetSymbolAddress((void**)&pwkl, g_wkl);
  cudaGetSymbolAddress((void**)&pwvh, g_wvh);
  cudaGetSymbolAddress((void**)&pwvl, g_wvl);
  cudaGetSymbolAddress((void**)&pwoh, g_woh);
  cudaGetSymbolAddress((void**)&pwol, g_wol);
  cudaGetSymbolAddress((void**)&padjb, g_adjb);

  const float QS = 0.18033688011112042f;   // 0.125 * log2(e)

  prep_kernel<<<3072, 256>>>(adj, padjb, x, pxh, pxl, pxf,
      Wq, Wk, Wv, Wo,
      pwqh, pwql, pwkh, pwkl, pwvh, pwvl, pwoh, pwol, QS);

  cudaFuncSetAttribute(qkv_hmma_kernel, cudaFuncAttributeMaxDynamicSharedMemorySize,
                       GEMM_SMEM);
  qkv_hmma_kernel<<<dim3((BATCH*SEQ)/64, 6), 128, GEMM_SMEM>>>(
      pxh, pxl, pxf, pwqh, pwql, pwkh, pwkl, pwvh, pwvl, bq, bk, bv,
      pqf, pkh, pkl, pvh, QS);

  cudaFuncSetAttribute(attn_hmma_kernel, cudaFuncAttributeMaxDynamicSharedMemorySize,
                       SM_ATTN);
  const dim3 ga(SEQ / 64, NH, BATCH);
  attn_hmma_kernel<<<ga, 128, SM_ATTN>>>(pqf, pkh, pkl, pvh, padjb, pch, pcl);

  cudaFuncSetAttribute(o_ln_kernel, cudaFuncAttributeMaxDynamicSharedMemorySize,
                       O_SMEM);
  o_ln_kernel<<<(BATCH*SEQ)/64, 256, O_SMEM>>>(
      pch, pcl, pwoh, pwol, bo, x, gamma, beta, out);
}